// round 1
// baseline (speedup 1.0000x reference)
#include <cuda_runtime.h>
#include <cuda_fp16.h>
#include <mma.h>

using namespace nvcuda;

#define G      24     // group size (rotations)
#define CIN    512
#define COUT   512
#define BMAX   2048

#define BM 128
#define BN 128
#define BK 32

// Scratch (device globals — no allocation allowed in kernel_launch)
__device__ __half g_xh[(long)BMAX * G * CIN];          // x in fp16, [B,24,CIN]
__device__ __half g_wt[(long)G * CIN * COUT];          // W^T fp16, [(r*CIN+c), o]
__device__ int    g_jmap[G * G];                       // jmap[i*G + r] = j

// ---------------------------------------------------------------------------
// jmap[i][r] = unique j with pair_orbit[i,j] == r
__global__ void jmap_kernel(const int* __restrict__ pair_orbit) {
    int t = threadIdx.x;
    if (t < G * G) {
        int i = t / G, j = t % G;
        int r = pair_orbit[i * G + j];
        g_jmap[i * G + r] = j;
    }
}

// x fp32 -> fp16 (coalesced both sides)
__global__ void convert_x_kernel(const float* __restrict__ x, long n) {
    long idx = ((long)blockIdx.x * blockDim.x + threadIdx.x) * 4;
    if (idx < n) {
        float4 v = *reinterpret_cast<const float4*>(x + idx);
        __half2 a = __floats2half2_rn(v.x, v.y);
        __half2 b = __floats2half2_rn(v.z, v.w);
        *reinterpret_cast<__half2*>(g_xh + idx)     = a;
        *reinterpret_cast<__half2*>(g_xh + idx + 2) = b;
    }
}

// weight [o, c, r] fp32 -> g_wt [(r*CIN + c) * COUT + o] fp16
// threads walk weight linearly (coalesced reads); writes are scattered (OK for now)
__global__ void convert_w_kernel(const float* __restrict__ w, int nr, long n) {
    long t = (long)blockIdx.x * blockDim.x + threadIdx.x;
    if (t < n) {
        int r = (int)(t % nr);
        long t2 = t / nr;
        int c = (int)(t2 % CIN);
        int o = (int)(t2 / CIN);
        g_wt[((long)r * CIN + c) * COUT + o] = __float2half_rn(w[t]);
    }
}

// ---------------------------------------------------------------------------
// GEMM: out[(b,i), o] = sum_k A[(b,i),k] * Wt[k,o],  k = r*CIN + c,
//       A[(b,i), r*CIN+c] = g_xh[b, jmap[i][r], c]  (gathered at load time)
// Block: BM=128 x BN=128, BK=32, 256 threads (8 warps, 4x2 warp grid,
// each warp 32x64 via 2x4 wmma 16x16x16 fragments).
__global__ __launch_bounds__(256) void gemm_kernel(float* __restrict__ out, int nr, int Bsz) {
    __shared__ __align__(16) __half As[BM][BK + 8];   // ldm 40 (mult of 8)
    __shared__ __align__(16) __half Bs[BK][BN + 8];   // ldm 136 (mult of 8)
    __shared__ int sj[G];

    const int i  = blockIdx.z;
    const int b0 = blockIdx.y * BM;
    const int o0 = blockIdx.x * BN;
    const int tid  = threadIdx.x;
    const int warp = tid >> 5;
    const int wm = warp >> 1;      // 0..3
    const int wn = warp & 1;       // 0..1

    if (tid < G) sj[tid] = g_jmap[i * G + tid];

    wmma::fragment<wmma::accumulator, 16, 16, 16, float> acc[2][4];
#pragma unroll
    for (int a = 0; a < 2; a++)
#pragma unroll
        for (int b = 0; b < 4; b++) wmma::fill_fragment(acc[a][b], 0.0f);

    __syncthreads();

    const int KT = nr * CIN;
    for (int k0 = 0; k0 < KT; k0 += BK) {
        const int r  = k0 >> 9;           // CIN = 512
        const int c0 = k0 & (CIN - 1);
        const int j  = sj[r];

        // Load A tile: 128 rows x 32 halves, 16B vectors, 2 per thread
#pragma unroll
        for (int v = 0; v < 2; v++) {
            int vid = tid * 2 + v;        // 0..511
            int m   = vid >> 2;           // 0..127
            int c8  = (vid & 3) * 8;      // 0,8,16,24
            const __half* src = g_xh + (((long)(b0 + m)) * G + j) * CIN + c0 + c8;
            *reinterpret_cast<uint4*>(&As[m][c8]) = *reinterpret_cast<const uint4*>(src);
        }
        // Load B tile: 32 rows x 128 halves, 2 vectors per thread
#pragma unroll
        for (int v = 0; v < 2; v++) {
            int vid = tid * 2 + v;        // 0..511
            int kk  = vid >> 4;           // 0..31
            int n8  = (vid & 15) * 8;     // 0..120
            const __half* src = g_wt + (long)(k0 + kk) * COUT + o0 + n8;
            *reinterpret_cast<uint4*>(&Bs[kk][n8]) = *reinterpret_cast<const uint4*>(src);
        }
        __syncthreads();

#pragma unroll
        for (int ks = 0; ks < BK; ks += 16) {
            wmma::fragment<wmma::matrix_a, 16, 16, 16, __half, wmma::row_major> af[2];
            wmma::fragment<wmma::matrix_b, 16, 16, 16, __half, wmma::row_major> bf[4];
#pragma unroll
            for (int a = 0; a < 2; a++)
                wmma::load_matrix_sync(af[a], &As[wm * 32 + a * 16][ks], BK + 8);
#pragma unroll
            for (int b = 0; b < 4; b++)
                wmma::load_matrix_sync(bf[b], &Bs[ks][wn * 64 + b * 16], BN + 8);
#pragma unroll
            for (int a = 0; a < 2; a++)
#pragma unroll
                for (int b = 0; b < 4; b++)
                    wmma::mma_sync(acc[a][b], af[a], bf[b], acc[a][b]);
        }
        __syncthreads();
    }

    // Store: out[(b0+m)*G*COUT + i*COUT + (o0+n)], row stride between m rows = G*COUT
#pragma unroll
    for (int a = 0; a < 2; a++)
#pragma unroll
        for (int b = 0; b < 4; b++) {
            int m = b0 + wm * 32 + a * 16;
            int o = o0 + wn * 64 + b * 16;
            float* p = out + ((long)m * G + i) * COUT + o;
            wmma::store_matrix_sync(p, acc[a][b], (unsigned)(G * COUT), wmma::mem_row_major);
        }
}

// out += bias broadcast over last dim (vectorized)
__global__ void bias_kernel(const float* __restrict__ bias, float* __restrict__ out, long n4) {
    long t = (long)blockIdx.x * blockDim.x + threadIdx.x;
    if (t < n4) {
        long idx = t * 4;
        float4 v = *reinterpret_cast<float4*>(out + idx);
        int o = (int)(idx & (COUT - 1));
        v.x += bias[o];
        v.y += bias[o + 1];
        v.z += bias[o + 2];
        v.w += bias[o + 3];
        *reinterpret_cast<float4*>(out + idx) = v;
    }
}

// ---------------------------------------------------------------------------
extern "C" void kernel_launch(void* const* d_in, const int* in_sizes, int n_in,
                              void* d_out, int out_size) {
    const float* x          = (const float*)d_in[0];
    const float* weight     = (const float*)d_in[1];
    const float* bias       = (const float*)d_in[2];
    const int*   pair_orbit = (const int*)d_in[3];
    float* out = (float*)d_out;

    const long xn = (long)in_sizes[0];                 // B*24*512
    const long wn = (long)in_sizes[1];                 // 512*512*nr
    const int  nr = (int)(wn / ((long)COUT * CIN));    // = 24
    const int  Bsz = (int)(xn / ((long)G * CIN));      // = 2048

    jmap_kernel<<<1, G * G>>>(pair_orbit);
    convert_x_kernel<<<(unsigned)((xn / 4 + 255) / 256), 256>>>(x, xn);
    convert_w_kernel<<<(unsigned)((wn + 255) / 256), 256>>>(weight, nr, wn);

    dim3 grid(COUT / BN, Bsz / BM, G);   // 4 x 16 x 24 = 1536 blocks
    gemm_kernel<<<grid, 256>>>(out, nr, Bsz);

    const long on = (long)out_size;
    bias_kernel<<<(unsigned)((on / 4 + 255) / 256), 256>>>(bias, out, on / 4);
}

// round 2
// speedup vs baseline: 1.4870x; 1.4870x over previous
#include <cuda_runtime.h>
#include <cuda_fp16.h>
#include <mma.h>

using namespace nvcuda;

#define G      24     // group size (rotations)
#define CIN    512
#define COUT   512
#define BMAX   2048

#define BM 128
#define BN 128
#define BK 32

// Scratch (device globals — no allocation allowed in kernel_launch)
__device__ __half g_xh[(long)BMAX * G * CIN];          // x in fp16, [B,24,CIN]
__device__ __half g_wt[(long)G * CIN * COUT];          // W^T fp16, [(r*CIN+c), o]
__device__ int    g_jmap[G * G];                       // jmap[i*G + r] = j

// ---------------------------------------------------------------------------
// jmap[i][r] = unique j with pair_orbit[i,j] == r
__global__ void jmap_kernel(const int* __restrict__ pair_orbit) {
    int t = threadIdx.x;
    if (t < G * G) {
        int i = t / G, j = t % G;
        int r = pair_orbit[i * G + j];
        g_jmap[i * G + r] = j;
    }
}

// x fp32 -> fp16 (coalesced both sides)
__global__ void convert_x_kernel(const float* __restrict__ x, long n) {
    long idx = ((long)blockIdx.x * blockDim.x + threadIdx.x) * 4;
    if (idx < n) {
        float4 v = *reinterpret_cast<const float4*>(x + idx);
        __half2 a = __floats2half2_rn(v.x, v.y);
        __half2 b = __floats2half2_rn(v.z, v.w);
        *reinterpret_cast<__half2*>(g_xh + idx)     = a;
        *reinterpret_cast<__half2*>(g_xh + idx + 2) = b;
    }
}

// weight [o, c, r] fp32 -> g_wt [(r*CIN + c) * COUT + o] fp16
// threads walk weight linearly (coalesced reads); writes are scattered (OK for now)
__global__ void convert_w_kernel(const float* __restrict__ w, int nr, long n) {
    long t = (long)blockIdx.x * blockDim.x + threadIdx.x;
    if (t < n) {
        int r = (int)(t % nr);
        long t2 = t / nr;
        int c = (int)(t2 % CIN);
        int o = (int)(t2 / CIN);
        g_wt[((long)r * CIN + c) * COUT + o] = __float2half_rn(w[t]);
    }
}

// ---------------------------------------------------------------------------
// GEMM: out[(b,i), o] = sum_k A[(b,i),k] * Wt[k,o],  k = r*CIN + c,
//       A[(b,i), r*CIN+c] = g_xh[b, jmap[i][r], c]  (gathered at load time)
// Block: BM=128 x BN=128, BK=32, 256 threads (8 warps, 4x2 warp grid,
// each warp 32x64 via 2x4 wmma 16x16x16 fragments).
__global__ __launch_bounds__(256) void gemm_kernel(float* __restrict__ out, int nr, int Bsz) {
    __shared__ __align__(16) __half As[BM][BK + 8];   // ldm 40 (mult of 8)
    __shared__ __align__(16) __half Bs[BK][BN + 8];   // ldm 136 (mult of 8)
    __shared__ int sj[G];

    const int i  = blockIdx.z;
    const int b0 = blockIdx.y * BM;
    const int o0 = blockIdx.x * BN;
    const int tid  = threadIdx.x;
    const int warp = tid >> 5;
    const int wm = warp >> 1;      // 0..3
    const int wn = warp & 1;       // 0..1

    if (tid < G) sj[tid] = g_jmap[i * G + tid];

    wmma::fragment<wmma::accumulator, 16, 16, 16, float> acc[2][4];
#pragma unroll
    for (int a = 0; a < 2; a++)
#pragma unroll
        for (int b = 0; b < 4; b++) wmma::fill_fragment(acc[a][b], 0.0f);

    __syncthreads();

    const int KT = nr * CIN;
    for (int k0 = 0; k0 < KT; k0 += BK) {
        const int r  = k0 >> 9;           // CIN = 512
        const int c0 = k0 & (CIN - 1);
        const int j  = sj[r];

        // Load A tile: 128 rows x 32 halves, 16B vectors, 2 per thread
#pragma unroll
        for (int v = 0; v < 2; v++) {
            int vid = tid * 2 + v;        // 0..511
            int m   = vid >> 2;           // 0..127
            int c8  = (vid & 3) * 8;      // 0,8,16,24
            const __half* src = g_xh + (((long)(b0 + m)) * G + j) * CIN + c0 + c8;
            *reinterpret_cast<uint4*>(&As[m][c8]) = *reinterpret_cast<const uint4*>(src);
        }
        // Load B tile: 32 rows x 128 halves, 2 vectors per thread
#pragma unroll
        for (int v = 0; v < 2; v++) {
            int vid = tid * 2 + v;        // 0..511
            int kk  = vid >> 4;           // 0..31
            int n8  = (vid & 15) * 8;     // 0..120
            const __half* src = g_wt + (long)(k0 + kk) * COUT + o0 + n8;
            *reinterpret_cast<uint4*>(&Bs[kk][n8]) = *reinterpret_cast<const uint4*>(src);
        }
        __syncthreads();

#pragma unroll
        for (int ks = 0; ks < BK; ks += 16) {
            wmma::fragment<wmma::matrix_a, 16, 16, 16, __half, wmma::row_major> af[2];
            wmma::fragment<wmma::matrix_b, 16, 16, 16, __half, wmma::row_major> bf[4];
#pragma unroll
            for (int a = 0; a < 2; a++)
                wmma::load_matrix_sync(af[a], &As[wm * 32 + a * 16][ks], BK + 8);
#pragma unroll
            for (int b = 0; b < 4; b++)
                wmma::load_matrix_sync(bf[b], &Bs[ks][wn * 64 + b * 16], BN + 8);
#pragma unroll
            for (int a = 0; a < 2; a++)
#pragma unroll
                for (int b = 0; b < 4; b++)
                    wmma::mma_sync(acc[a][b], af[a], bf[b], acc[a][b]);
        }
        __syncthreads();
    }

    // Store: out[(b0+m)*G*COUT + i*COUT + (o0+n)], row stride between m rows = G*COUT
#pragma unroll
    for (int a = 0; a < 2; a++)
#pragma unroll
        for (int b = 0; b < 4; b++) {
            int m = b0 + wm * 32 + a * 16;
            int o = o0 + wn * 64 + b * 16;
            float* p = out + ((long)m * G + i) * COUT + o;
            wmma::store_matrix_sync(p, acc[a][b], (unsigned)(G * COUT), wmma::mem_row_major);
        }
}

// out += bias broadcast over last dim (vectorized)
__global__ void bias_kernel(const float* __restrict__ bias, float* __restrict__ out, long n4) {
    long t = (long)blockIdx.x * blockDim.x + threadIdx.x;
    if (t < n4) {
        long idx = t * 4;
        float4 v = *reinterpret_cast<float4*>(out + idx);
        int o = (int)(idx & (COUT - 1));
        v.x += bias[o];
        v.y += bias[o + 1];
        v.z += bias[o + 2];
        v.w += bias[o + 3];
        *reinterpret_cast<float4*>(out + idx) = v;
    }
}

// ---------------------------------------------------------------------------
extern "C" void kernel_launch(void* const* d_in, const int* in_sizes, int n_in,
                              void* d_out, int out_size) {
    const float* x          = (const float*)d_in[0];
    const float* weight     = (const float*)d_in[1];
    const float* bias       = (const float*)d_in[2];
    const int*   pair_orbit = (const int*)d_in[3];
    float* out = (float*)d_out;

    const long xn = (long)in_sizes[0];                 // B*24*512
    const long wn = (long)in_sizes[1];                 // 512*512*nr
    const int  nr = (int)(wn / ((long)COUT * CIN));    // = 24
    const int  Bsz = (int)(xn / ((long)G * CIN));      // = 2048

    jmap_kernel<<<1, G * G>>>(pair_orbit);
    convert_x_kernel<<<(unsigned)((xn / 4 + 255) / 256), 256>>>(x, xn);
    convert_w_kernel<<<(unsigned)((wn + 255) / 256), 256>>>(weight, nr, wn);

    dim3 grid(COUT / BN, Bsz / BM, G);   // 4 x 16 x 24 = 1536 blocks
    gemm_kernel<<<grid, 256>>>(out, nr, Bsz);

    const long on = (long)out_size;
    bias_kernel<<<(unsigned)((on / 4 + 255) / 256), 256>>>(bias, out, on / 4);
}

// round 4
// speedup vs baseline: 1.8745x; 1.2606x over previous
#include <cuda_runtime.h>
#include <cuda_fp16.h>
#include <mma.h>
#include <cstdint>

using namespace nvcuda;

#define G      24
#define CIN    512
#define COUT   512
#define BMAX   2048
#define KT     (G * CIN)          // 12288

#define BM 128
#define BN 256
#define BK 32
#define NSTAGE 4
#define NCHUNK (KT / BK)          // 384

// padded smem rows
#define LDA (BK + 8)              // 40 halves  (80B, 16B-aligned rows)
#define LDB (BN + 8)              // 264 halves (528B, 16B-aligned rows)
#define ASTG (BM * LDA * 2)       // 10240 B per stage
#define BSTG (BK * LDB * 2)       // 16896 B per stage
#define SM_BOFF (NSTAGE * ASTG)   // 40960
#define SM_SJ   (SM_BOFF + NSTAGE * BSTG)   // 108544
#define SMEM_TOTAL (SM_SJ + 96)

// ---- scratch (no allocation allowed) --------------------------------------
__device__ __half g_xh[(long)BMAX * G * CIN];   // x fp16 [b][j][c]
__device__ __half g_wt[(long)KT * COUT];        // W^T fp16 [k][o], k = r*CIN+c
__device__ int    g_jmap[G * G];                // jmap[i*G + r] = j

// ---- helpers --------------------------------------------------------------
__device__ __forceinline__ uint32_t smem_u32(const void* p) {
    uint32_t a;
    asm("{ .reg .u64 t; cvta.to.shared.u64 t, %1; cvt.u32.u64 %0, t; }" : "=r"(a) : "l"(p));
    return a;
}
__device__ __forceinline__ void cp_async16(uint32_t saddr, const void* gaddr) {
    asm volatile("cp.async.cg.shared.global [%0], [%1], 16;" :: "r"(saddr), "l"(gaddr) : "memory");
}
__device__ __forceinline__ void cp_commit() {
    asm volatile("cp.async.commit_group;" ::: "memory");
}
template <int N>
__device__ __forceinline__ void cp_wait() {
    asm volatile("cp.async.wait_group %0;" :: "n"(N) : "memory");
}

// ---- prep kernels ---------------------------------------------------------
__global__ void jmap_kernel(const int* __restrict__ pair_orbit) {
    int t = threadIdx.x;
    if (t < G * G) {
        int i = t / G, j = t % G;
        g_jmap[i * G + pair_orbit[i * G + j]] = j;
    }
}

__global__ void convert_x_kernel(const float* __restrict__ x, long n) {
    long idx = ((long)blockIdx.x * blockDim.x + threadIdx.x) * 4;
    if (idx < n) {
        float4 v = *reinterpret_cast<const float4*>(x + idx);
        *reinterpret_cast<__half2*>(g_xh + idx)     = __floats2half2_rn(v.x, v.y);
        *reinterpret_cast<__half2*>(g_xh + idx + 2) = __floats2half2_rn(v.z, v.w);
    }
}

// weight [o, c, r] fp32 -> g_wt [(r*CIN + c) * COUT + o] fp16
__global__ void convert_w_kernel(const float* __restrict__ w, int nr, long n) {
    long t = (long)blockIdx.x * blockDim.x + threadIdx.x;
    if (t < n) {
        int r = (int)(t % nr);
        long t2 = t / nr;
        int c = (int)(t2 % CIN);
        int o = (int)(t2 / CIN);
        g_wt[((long)r * CIN + c) * COUT + o] = __float2half_rn(w[t]);
    }
}

// ---- main GEMM ------------------------------------------------------------
// out[(b,i), o] = sum_k A[(b,i),k] * Wt[k,o];  A row gathered via jmap.
// 256 threads, 8 warps as 2(m) x 4(n), warp tile 64x64; cp.async 4-stage.
__global__ void __launch_bounds__(256, 1)
gemm_kernel(float* __restrict__ out, int nbt) {
    extern __shared__ char smem[];
    const uint32_t sb = smem_u32(smem);
    const int tid = threadIdx.x;
    const int wid = tid >> 5;
    const int wm = wid & 1;            // 0..1
    const int wn = wid >> 1;           // 0..3

    const int i  = blockIdx.y / nbt;
    const int b0 = (blockIdx.y - i * nbt) * BM;
    const int o0 = blockIdx.x * BN;

    int* sj = (int*)(smem + SM_SJ);
    if (tid < G) sj[tid] = g_jmap[i * G + tid];
    __syncthreads();

    const __half* Abase = g_xh + (long)b0 * (G * CIN);
    const __half* Bbase = g_wt + o0;

    // prologue: stages 0..2
#pragma unroll
    for (int ch = 0; ch < NSTAGE - 1; ch++) {
        const int s = ch;
        const int r = ch >> 4, c0 = (ch & 15) << 5;
        const int j = sj[r];
        const __half* Ab = Abase + j * CIN + c0;
#pragma unroll
        for (int v = 0; v < 2; v++) {
            int q = v * 256 + tid;               // 0..511
            int m = q >> 2, kc = q & 3;
            cp_async16(sb + s * ASTG + (m * LDA + kc * 8) * 2,
                       Ab + (long)m * (G * CIN) + kc * 8);
        }
        const __half* Bb = Bbase + (long)(ch << 5) * COUT;
#pragma unroll
        for (int v = 0; v < 4; v++) {
            int q = v * 256 + tid;               // 0..1023
            int kk = q >> 5, nc = q & 31;
            cp_async16(sb + SM_BOFF + s * BSTG + (kk * LDB + nc * 8) * 2,
                       Bb + (long)kk * COUT + nc * 8);
        }
        cp_commit();
    }

    wmma::fragment<wmma::accumulator, 16, 16, 16, float> acc[4][4];
#pragma unroll
    for (int a = 0; a < 4; a++)
#pragma unroll
        for (int b = 0; b < 4; b++) wmma::fill_fragment(acc[a][b], 0.0f);

    for (int ch = 0; ch < NCHUNK; ch++) {
        cp_wait<NSTAGE - 2>();
        __syncthreads();

        // prefetch chunk ch+3 into stage (ch+3)%4
        const int pf = ch + NSTAGE - 1;
        if (pf < NCHUNK) {
            const int s = pf & (NSTAGE - 1);
            const int r = pf >> 4, c0 = (pf & 15) << 5;
            const int j = sj[r];
            const __half* Ab = Abase + j * CIN + c0;
#pragma unroll
            for (int v = 0; v < 2; v++) {
                int q = v * 256 + tid;
                int m = q >> 2, kc = q & 3;
                cp_async16(sb + s * ASTG + (m * LDA + kc * 8) * 2,
                           Ab + (long)m * (G * CIN) + kc * 8);
            }
            const __half* Bb = Bbase + (long)(pf << 5) * COUT;
#pragma unroll
            for (int v = 0; v < 4; v++) {
                int q = v * 256 + tid;
                int kk = q >> 5, nc = q & 31;
                cp_async16(sb + SM_BOFF + s * BSTG + (kk * LDB + nc * 8) * 2,
                           Bb + (long)kk * COUT + nc * 8);
            }
            cp_commit();
        }

        // compute stage ch%4
        const int s = ch & (NSTAGE - 1);
        const __half* As = (const __half*)(smem + s * ASTG);
        const __half* Bs = (const __half*)(smem + SM_BOFF + s * BSTG);
#pragma unroll
        for (int ks = 0; ks < BK; ks += 16) {
            wmma::fragment<wmma::matrix_a, 16, 16, 16, __half, wmma::row_major> af[4];
            wmma::fragment<wmma::matrix_b, 16, 16, 16, __half, wmma::row_major> bf[4];
#pragma unroll
            for (int a = 0; a < 4; a++)
                wmma::load_matrix_sync(af[a], As + (wm * 64 + a * 16) * LDA + ks, LDA);
#pragma unroll
            for (int b = 0; b < 4; b++)
                wmma::load_matrix_sync(bf[b], Bs + ks * LDB + wn * 64 + b * 16, LDB);
#pragma unroll
            for (int a = 0; a < 4; a++)
#pragma unroll
                for (int b = 0; b < 4; b++)
                    wmma::mma_sync(acc[a][b], af[a], bf[b], acc[a][b]);
        }
    }

    // epilogue: out[(b0+m)*G*COUT + i*COUT + o]
#pragma unroll
    for (int a = 0; a < 4; a++)
#pragma unroll
        for (int b = 0; b < 4; b++) {
            int m = b0 + wm * 64 + a * 16;
            int o = o0 + wn * 64 + b * 16;
            float* p = out + ((long)m * G + i) * COUT + o;
            wmma::store_matrix_sync(p, acc[a][b], (unsigned)(G * COUT), wmma::mem_row_major);
        }
}

// out += bias broadcast over last dim (vectorized)
__global__ void bias_kernel(const float* __restrict__ bias, float* __restrict__ out, long n4) {
    long t = (long)blockIdx.x * blockDim.x + threadIdx.x;
    if (t < n4) {
        long idx = t * 4;
        float4 v = *reinterpret_cast<float4*>(out + idx);
        int o = (int)(idx & (COUT - 1));
        v.x += bias[o];
        v.y += bias[o + 1];
        v.z += bias[o + 2];
        v.w += bias[o + 3];
        *reinterpret_cast<float4*>(out + idx) = v;
    }
}

// ---------------------------------------------------------------------------
extern "C" void kernel_launch(void* const* d_in, const int* in_sizes, int n_in,
                              void* d_out, int out_size) {
    const float* x          = (const float*)d_in[0];
    const float* weight     = (const float*)d_in[1];
    const float* bias       = (const float*)d_in[2];
    const int*   pair_orbit = (const int*)d_in[3];
    float* out = (float*)d_out;

    const long xn  = (long)in_sizes[0];
    const long wn  = (long)in_sizes[1];
    const int  nr  = (int)(wn / ((long)COUT * CIN));   // 24
    const int  Bsz = (int)(xn / ((long)G * CIN));      // 2048
    const int  nbt = Bsz / BM;                         // 16

    jmap_kernel<<<1, G * G>>>(pair_orbit);
    convert_x_kernel<<<(unsigned)((xn / 4 + 255) / 256), 256>>>(x, xn);
    convert_w_kernel<<<(unsigned)((wn + 255) / 256), 256>>>(weight, nr, wn);

    cudaFuncSetAttribute(gemm_kernel, cudaFuncAttributeMaxDynamicSharedMemorySize,
                         SMEM_TOTAL);
    dim3 grid(COUT / BN, G * nbt);    // 2 x 384 = 768 CTAs
    gemm_kernel<<<grid, 256, SMEM_TOTAL>>>(out, nbt);

    const long on = (long)out_size;
    bias_kernel<<<(unsigned)((on / 4 + 255) / 256), 256>>>(bias, out, on / 4);
}